// round 9
// baseline (speedup 1.0000x reference)
#include <cuda_runtime.h>

#define B_ 64
#define T_ 1024
#define C_ 2
#define N_ 128

// Per-chain named barrier: chain cid syncs its own 128 threads on barrier 1+cid.
// (Barrier 0 is left for __syncthreads.)
#define BAR_CHAIN(cid) asm volatile("bar.sync %0, 128;" :: "r"(1 + (cid)) : "memory")

// ---- packed f32x2 helpers (Blackwell sm_100+) ----
__device__ __forceinline__ unsigned long long pk2(float lo, float hi) {
    unsigned long long r;
    asm("mov.b64 %0, {%1, %2};" : "=l"(r) : "f"(lo), "f"(hi));
    return r;
}
__device__ __forceinline__ void upk2(unsigned long long v, float& lo, float& hi) {
    asm("mov.b64 {%0, %1}, %2;" : "=f"(lo), "=f"(hi) : "l"(v));
}
__device__ __forceinline__ void fma2(unsigned long long& acc, unsigned long long a,
                                     unsigned long long b) {
    asm("fma.rn.f32x2 %0, %1, %2, %0;" : "+l"(acc) : "l"(a), "l"(b));
}
__device__ __forceinline__ unsigned long long add2(unsigned long long a,
                                                   unsigned long long b) {
    unsigned long long r;
    asm("add.rn.f32x2 %0, %1, %2;" : "=l"(r) : "l"(a), "l"(b));
    return r;
}

// Packed dot over ALL 128 rows: S_j = sum_i r_i * E_ij.
__device__ __forceinline__ float dot128(const float* rbuf,
                                        const unsigned long long* e2) {
    unsigned long long a0 = 0ull, a1 = 0ull, a2 = 0ull, a3 = 0ull;
    const ulonglong2* pv = reinterpret_cast<const ulonglong2*>(rbuf);
#pragma unroll
    for (int k = 0; k < 32; ++k) {       // 32 * 4 floats = 128 rows
        ulonglong2 v = pv[k];
        if ((k & 1) == 0) { fma2(a0, e2[2 * k], v.x); fma2(a1, e2[2 * k + 1], v.y); }
        else              { fma2(a2, e2[2 * k], v.x); fma2(a3, e2[2 * k + 1], v.y); }
    }
    a0 = add2(a0, a1);
    a2 = add2(a2, a3);
    a0 = add2(a0, a2);
    float lo, hi;
    upk2(a0, lo, hi);
    return lo + hi;
}

// One CTA = both C-chains of one batch element b (same len -> same trip count).
// Warps 0-3: chain 0 (threads 0-127); warps 4-7: chain 1 (threads 128-255).
// Each chain steps on its OWN named barrier, so the two chains run decoupled:
// each SMSP hosts one warp of each chain, and one chain's FFMA2 stream fills
// the other's barrier/LDS latency bubbles.
__global__ void __launch_bounds__(256, 1)
crf_fwd_kernel(const float* __restrict__ emissions,   // [B,T,C,N]
               const int*   __restrict__ lengths,     // [B]
               const float* __restrict__ trans,       // [1,C,N,N]
               const float* __restrict__ start_t,     // [1,C,N]
               const float* __restrict__ end_t,       // [1,C,N]
               float*       __restrict__ out)         // [B,C]
{
    const int tid = threadIdx.x;
    const int c   = tid >> 7;           // chain within CTA (0 or 1)
    const int j   = tid & 127;          // tag column this thread owns
    const int b   = blockIdx.x;
    const int wq  = (tid >> 5) & 3;     // warp-quarter within chain
    const int len = lengths[b];         // in [T/2, T], shared by both chains

    __shared__ __align__(16) float r_sh[2][C_][N_];   // [buf][chain][tag]
    __shared__ __align__(16) float red_sh[C_][4];

    // ---- E packed: e2[m] = (exp(trans[c,2m,j]), exp(trans[c,2m+1,j])) ----
    unsigned long long e2[64];
    {
        const float* tb = trans + (size_t)c * N_ * N_ + j;
#pragma unroll
        for (int m = 0; m < 64; ++m) {
            float lo = __expf(tb[(size_t)(2 * m) * N_]);
            float hi = __expf(tb[(size_t)(2 * m + 1) * N_]);
            e2[m] = pk2(lo, hi);
        }
    }

    const float* ebase = emissions + ((size_t)b * T_ * C_ + c) * N_ + j;
    const int estride = C_ * N_;

    // ---- init: r_0 = exp(start + emit_0), unnormalized ----
    r_sh[0][c][j] = __expf(start_t[c * N_ + j] + ebase[0]);
    int kacc = 0;                       // sum of biased exponents (exact norm log)

    // ---- RAW emission ring, depth 8; slot (t & 7) holds raw emit_t ----
    float ering[8];
#pragma unroll
    for (int d = 1; d <= 8; ++d) {
        int tt = d; tt = (tt > T_ - 1) ? (T_ - 1) : tt;
        ering[d & 7] = __ldg(ebase + (size_t)tt * estride);
    }
    BAR_CHAIN(c);                       // r_0 visible within this chain

    // ---- main scan, clamp-free: refills reach t+15 <= len-1 <= T-1 ----
    int t = 1;
#pragma unroll 1
    for (; t + 15 < len; t += 8) {      // t stays ≡ 1 (mod 8)
#pragma unroll
        for (int u = 0; u < 8; ++u) {
            const int cur  = (1 + u) & 1;   // compile-time buffer parity
            const int prv  = cur ^ 1;
            const int slot = (1 + u) & 7;   // compile-time ring slot
            const int tq   = t + u;

            // power-of-2 normalizer from previous step's r[0] (broadcast LDS).
            float cn = r_sh[prv][c][0];
            int   ke = (__float_as_int(cn) >> 23) & 0xff;
            float inv = __int_as_float((254 - ke) << 23);
            kacc += ke;

            // emission: exp of an 8-step-old raw value; refill 8 ahead (raw)
            float em = __expf(ering[slot]);
            ering[slot] = __ldg(ebase + (size_t)(tq + 8) * estride);

            float S = dot128(r_sh[prv][c], e2);
            r_sh[cur][c][j] = S * (em * inv);
            BAR_CHAIN(c);
        }
    }
    // tail (≤ 15 steps), runtime parity, clamped refills
#pragma unroll 1
    for (; t < len; ++t) {
        const int cur = t & 1;
        const int prv = cur ^ 1;
        float cn = r_sh[prv][c][0];
        int   ke = (__float_as_int(cn) >> 23) & 0xff;
        float inv = __int_as_float((254 - ke) << 23);
        kacc += ke;
        float em = __expf(ering[t & 7]);
        int tt = t + 8; tt = (tt > T_ - 1) ? (T_ - 1) : tt;
        ering[t & 7] = __ldg(ebase + (size_t)tt * estride);
        float S = dot128(r_sh[prv][c], e2);
        r_sh[cur][c][j] = S * (em * inv);
        BAR_CHAIN(c);
    }

    // ---- finalize: logZ = (kacc - 127*(len-1))*ln2 + log( sum_j r_j e^{end_j} ) ----
    float v = r_sh[(len - 1) & 1][c][j] * __expf(end_t[c * N_ + j]);
    float s = v;
#pragma unroll
    for (int o = 16; o > 0; o >>= 1)
        s += __shfl_xor_sync(0xffffffffu, s, o);
    if ((j & 31) == 0) red_sh[c][wq] = s;
    BAR_CHAIN(c);
    if (j == 0) {
        float Sf = (red_sh[c][0] + red_sh[c][1]) + (red_sh[c][2] + red_sh[c][3]);
        float logK = (float)(kacc - 127 * (len - 1)) * 0.6931471805599453f;
        out[b * C_ + c] = logK + logf(Sf);
    }
}

extern "C" void kernel_launch(void* const* d_in, const int* in_sizes, int n_in,
                              void* d_out, int out_size) {
    // Identify inputs by element count (robust to metadata ordering).
    const float* emissions = nullptr;
    const int*   lengths   = nullptr;
    const float* trans     = nullptr;
    const float* start_t   = nullptr;
    const float* end_t     = nullptr;

    for (int i = 0; i < n_in; ++i) {
        int sz = in_sizes[i];
        if (sz == B_ * T_ * C_ * N_)      emissions = (const float*)d_in[i];
        else if (sz == B_)                lengths   = (const int*)d_in[i];
        else if (sz == C_ * N_ * N_)      trans     = (const float*)d_in[i];
    }
    if (n_in > 3 && in_sizes[3] == C_ * N_) start_t = (const float*)d_in[3];
    for (int i = 0; i < n_in; ++i) {
        if (in_sizes[i] == C_ * N_ && (const float*)d_in[i] != start_t)
            end_t = (const float*)d_in[i];
    }
    if (!start_t) {
        for (int i = 0; i < n_in; ++i)
            if (in_sizes[i] == C_ * N_) { start_t = (const float*)d_in[i]; break; }
        for (int i = 0; i < n_in; ++i)
            if (in_sizes[i] == C_ * N_ && (const float*)d_in[i] != start_t)
                end_t = (const float*)d_in[i];
    }

    float* out = (float*)d_out;
    crf_fwd_kernel<<<B_, 256>>>(emissions, lengths, trans, start_t, end_t, out);
}

// round 10
// speedup vs baseline: 2.2263x; 2.2263x over previous
#include <cuda_runtime.h>
#include <cuda_fp16.h>

#define B_ 64
#define T_ 1024
#define C_ 2
#define N_ 128

// fp16 dot over ALL 128 rows: S_j = sum_i r_i * E_ij.
// rbuf: 128 halves (256B, 16B-aligned). e2h[m] packs rows (2m, 2m+1) of E col j.
// 4 independent half2 accumulators (each half sums 16 terms; bounded << 65504).
__device__ __forceinline__ float dot128_h(const __half* rbuf, const __half2* e2h) {
    const uint4* pv = reinterpret_cast<const uint4*>(rbuf);
    __half2 a0 = __float2half2_rn(0.f), a1 = a0, a2 = a0, a3 = a0;
#pragma unroll
    for (int k = 0; k < 16; ++k) {       // 16 x LDS.128 = 128 rows
        uint4 v = pv[k];
        a0 = __hfma2(e2h[4 * k + 0], *reinterpret_cast<const __half2*>(&v.x), a0);
        a1 = __hfma2(e2h[4 * k + 1], *reinterpret_cast<const __half2*>(&v.y), a1);
        a2 = __hfma2(e2h[4 * k + 2], *reinterpret_cast<const __half2*>(&v.z), a2);
        a3 = __hfma2(e2h[4 * k + 3], *reinterpret_cast<const __half2*>(&v.w), a3);
    }
    float s0 = __low2float(a0) + __high2float(a0);
    float s1 = __low2float(a1) + __high2float(a1);
    float s2 = __low2float(a2) + __high2float(a2);
    float s3 = __low2float(a3) + __high2float(a3);
    return (s0 + s1) + (s2 + s3);
}

__global__ void __launch_bounds__(128, 1)
crf_fwd_kernel(const float* __restrict__ emissions,   // [B,T,C,N]
               const int*   __restrict__ lengths,     // [B]
               const float* __restrict__ trans,       // [1,C,N,N]
               const float* __restrict__ start_t,     // [1,C,N]
               const float* __restrict__ end_t,       // [1,C,N]
               float*       __restrict__ out)         // [B,C]
{
    const int j   = threadIdx.x;        // tag column this thread owns
    const int bc  = blockIdx.x;         // chain id
    const int b   = bc >> 1;
    const int c   = bc & 1;
    const int wid = j >> 5;
    const int len = lengths[b];         // in [T/2, T]

    __shared__ __align__(16) __half r_h[2][N_];   // scaled forward vector, fp16
    __shared__ __align__(16) float red_sh[4];

    // ---- E packed fp16: e2h[m] = (exp(trans[c,2m,j]), exp(trans[c,2m+1,j])) ----
    __half2 e2h[64];
    {
        const float* tb = trans + (size_t)c * N_ * N_ + j;
#pragma unroll
        for (int m = 0; m < 64; ++m) {
            float lo = __expf(tb[(size_t)(2 * m) * N_]);
            float hi = __expf(tb[(size_t)(2 * m + 1) * N_]);
            e2h[m] = __floats2half2_rn(lo, hi);
        }
    }

    const float* ebase = emissions + ((size_t)b * T_ * C_ + c) * N_ + j;
    const int estride = C_ * N_;

    // ---- init: r_0 = exp(start + emit_0)  (|.| in [e^-6, e^6] -> fp16 ok) ----
    r_h[0][j] = __float2half_rn(__expf(start_t[c * N_ + j] + ebase[0]));
    int kacc = 0;                       // sum of fp16 biased exponents of cn
    __syncthreads();

    // ---- RAW emission ring, depth 8; slot (t & 7) holds raw emit_t.
    //      __expf applied only at consumption (8 steps after the load). ----
    float ering[8];
#pragma unroll
    for (int d = 1; d <= 8; ++d) {
        int tt = d; tt = (tt > T_ - 1) ? (T_ - 1) : tt;
        ering[d & 7] = __ldg(ebase + (size_t)tt * estride);
    }

    // ---- main scan, clamp-free: refills reach t+15 <= len-1 <= T-1 ----
    // Normalization: inv = 2^(4-ke) with ke = biased fp16 exponent of r_prev[0].
    // Targets r[0] ~ 2^-4, keeping all r and fp16 partial sums in range.
    // Exact bookkeeping: logK = (kacc - 4*(len-1)) * ln2.
    int t = 1;
#pragma unroll 1
    for (; t + 15 < len; t += 8) {      // t stays ≡ 1 (mod 8)
#pragma unroll
        for (int u = 0; u < 8; ++u) {
            const int cur  = (1 + u) & 1;   // compile-time buffer parity
            const int prv  = cur ^ 1;
            const int slot = (1 + u) & 7;   // compile-time ring slot
            const int tq   = t + u;

            // pow-2 normalizer from previous step's r[0] (fp16 exponent bits)
            unsigned short ub = __half_as_ushort(r_h[prv][0]);
            int   ke  = (ub >> 10) & 0x1f;
            float inv = __int_as_float((131 - ke) << 23);   // 2^(4-ke), exact
            kacc += ke;

            // emission: exp of an 8-step-old raw value; refill 8 ahead (raw)
            float em = __expf(ering[slot]);
            ering[slot] = __ldg(ebase + (size_t)(tq + 8) * estride);

            float S = dot128_h(r_h[prv], e2h);
            r_h[cur][j] = __float2half_rn(S * (em * inv));
            __syncthreads();
        }
    }
    // tail (≤ 15 steps), runtime parity, clamped refills
#pragma unroll 1
    for (; t < len; ++t) {
        const int cur = t & 1;
        const int prv = cur ^ 1;
        unsigned short ub = __half_as_ushort(r_h[prv][0]);
        int   ke  = (ub >> 10) & 0x1f;
        float inv = __int_as_float((131 - ke) << 23);
        kacc += ke;
        float em = __expf(ering[t & 7]);
        int tt = t + 8; tt = (tt > T_ - 1) ? (T_ - 1) : tt;
        ering[t & 7] = __ldg(ebase + (size_t)tt * estride);
        float S = dot128_h(r_h[prv], e2h);
        r_h[cur][j] = __float2half_rn(S * (em * inv));
        __syncthreads();
    }

    // ---- finalize: logZ = (kacc - 4*(len-1))*ln2 + log( sum_j r_j e^{end_j} ) ----
    float v = __half2float(r_h[(len - 1) & 1][j]) * __expf(end_t[c * N_ + j]);
    float s = v;
#pragma unroll
    for (int o = 16; o > 0; o >>= 1)
        s += __shfl_xor_sync(0xffffffffu, s, o);
    if ((j & 31) == 0) red_sh[wid] = s;
    __syncthreads();
    if (j == 0) {
        float Sf = (red_sh[0] + red_sh[1]) + (red_sh[2] + red_sh[3]);
        float logK = (float)(kacc - 4 * (len - 1)) * 0.6931471805599453f;
        out[bc] = logK + logf(Sf);
    }
}

extern "C" void kernel_launch(void* const* d_in, const int* in_sizes, int n_in,
                              void* d_out, int out_size) {
    // Identify inputs by element count (robust to metadata ordering).
    const float* emissions = nullptr;
    const int*   lengths   = nullptr;
    const float* trans     = nullptr;
    const float* start_t   = nullptr;
    const float* end_t     = nullptr;

    for (int i = 0; i < n_in; ++i) {
        int sz = in_sizes[i];
        if (sz == B_ * T_ * C_ * N_)      emissions = (const float*)d_in[i];
        else if (sz == B_)                lengths   = (const int*)d_in[i];
        else if (sz == C_ * N_ * N_)      trans     = (const float*)d_in[i];
    }
    if (n_in > 3 && in_sizes[3] == C_ * N_) start_t = (const float*)d_in[3];
    for (int i = 0; i < n_in; ++i) {
        if (in_sizes[i] == C_ * N_ && (const float*)d_in[i] != start_t)
            end_t = (const float*)d_in[i];
    }
    if (!start_t) {
        for (int i = 0; i < n_in; ++i)
            if (in_sizes[i] == C_ * N_) { start_t = (const float*)d_in[i]; break; }
        for (int i = 0; i < n_in; ++i)
            if (in_sizes[i] == C_ * N_ && (const float*)d_in[i] != start_t)
                end_t = (const float*)d_in[i];
    }

    float* out = (float*)d_out;
    crf_fwd_kernel<<<B_ * C_, N_>>>(emissions, lengths, trans, start_t, end_t, out);
}